// round 1
// baseline (speedup 1.0000x reference)
#include <cuda_runtime.h>
#include <cuda_bf16.h>

// ---------------------------------------------------------------------------
// RGCN layer, fused.
// d_in:
//  0 node_feat            [N,32]  f32
//  1 total_target_relation[E,32]  f32
//  2 total_relation_embed [E,32]  f32
//  3 weight               [NB,32,32] f32
//  4 w_comp               [R,NB]  f32
//  5 self_loop_weight     [32,32] f32
//  6 A_w                  [32,128] f32
//  7 A_b                  [32]    f32
//  8 B_w                  [1,32]  f32
//  9 B_b                  [1]     f32
// 10 total_edge           [2,E]   i32
// 11 total_relation       [E]     i32
// out: [N,32] f32
// ---------------------------------------------------------------------------

#define IN_DIM  32
#define OUT_DIM 32
#define CAT_DIM 128   // 2*IN + 2*ATTN

// scratch for expanded per-relation weights: up to 256 relations * 32*32 floats
__device__ float g_relw[256 * IN_DIM * OUT_DIM];

// ---- kernel 1: rel_w[r,i,o] = sum_b w_comp[r,b] * weight[b,i,o] -------------
__global__ void k_expand_basis(const float* __restrict__ weight,
                               const float* __restrict__ w_comp,
                               int NB)
{
    int r = blockIdx.x;
    const float* wc = w_comp + r * NB;
    for (int io = threadIdx.x; io < IN_DIM * OUT_DIM; io += blockDim.x) {
        float acc = 0.f;
        for (int b = 0; b < NB; ++b)
            acc = fmaf(__ldg(wc + b), __ldg(weight + b * (IN_DIM * OUT_DIM) + io), acc);
        g_relw[r * (IN_DIM * OUT_DIM) + io] = acc;
    }
}

// ---- kernel 2: fused per-edge pipeline, persistent warps --------------------
__global__ void __launch_bounds__(256, 1)
k_edges(const float* __restrict__ node_feat,
        const float* __restrict__ ttr,     // total_target_relation
        const float* __restrict__ tre,     // total_relation_embed
        const float* __restrict__ slw,     // self_loop_weight [32,32]
        const float* __restrict__ A_w,     // [32,128]
        const float* __restrict__ A_b,     // [32]
        const float* __restrict__ B_w,     // [32]
        const float* __restrict__ B_b,     // [1]
        const int*   __restrict__ edges,   // [2,E]
        const int*   __restrict__ rels,    // [E]
        float*       __restrict__ out,     // [N,32]
        int E)
{
    const int lane   = threadIdx.x & 31;
    const int gw     = (int)((blockIdx.x * blockDim.x + threadIdx.x) >> 5);
    const int nwarps = (int)((gridDim.x * blockDim.x) >> 5);

    // persistent per-lane constants
    float a_row[CAT_DIM];                 // row `lane` of A_w
#pragma unroll
    for (int k = 0; k < CAT_DIM; ++k)
        a_row[k] = __ldg(A_w + lane * CAT_DIM + k);

    float slw_col[IN_DIM];                // column `lane` of self_loop_weight
#pragma unroll
    for (int i = 0; i < IN_DIM; ++i)
        slw_col[i] = __ldg(slw + i * OUT_DIM + lane);

    const float ab = __ldg(A_b + lane);
    const float bw = __ldg(B_w + lane);
    const float bb = __ldg(B_b);

    for (int e = gw; e < E; e += nwarps) {
        const int s_node = __ldg(edges + e);
        const int t_node = __ldg(edges + E + e);
        const int r      = __ldg(rels + e);

        const float4* sp  = (const float4*)(node_feat + (size_t)s_node * IN_DIM);
        const float4* tp  = (const float4*)(node_feat + (size_t)t_node * IN_DIM);
        const float4* rep = (const float4*)(tre + (size_t)e * IN_DIM);
        const float4* trp = (const float4*)(ttr + (size_t)e * IN_DIM);
        const float*  rw  = g_relw + (size_t)r * (IN_DIM * OUT_DIM);

        float h    = ab;    // attention pre-activation for feature `lane`
        float msg  = 0.f;   // relation-transformed message, output dim `lane`
        float curr = 0.f;   // self-loop transform, output dim `lane`

#pragma unroll
        for (int c = 0; c < IN_DIM / 4; ++c) {
            // same-address warp-broadcast loads: 1 line per instruction
            float4 s4  = __ldg(sp  + c);
            float4 t4  = __ldg(tp  + c);
            float4 re4 = __ldg(rep + c);
            float4 tr4 = __ldg(trp + c);

            float sv[4]  = {s4.x,  s4.y,  s4.z,  s4.w};
            float tv[4]  = {t4.x,  t4.y,  t4.z,  t4.w};
            float rev[4] = {re4.x, re4.y, re4.z, re4.w};
            float trv[4] = {tr4.x, tr4.y, tr4.z, tr4.w};

#pragma unroll
            for (int j = 0; j < 4; ++j) {
                const int i = 4 * c + j;
                h = fmaf(sv[j],  a_row[i],            h);
                h = fmaf(tv[j],  a_row[IN_DIM + i],   h);
                h = fmaf(rev[j], a_row[2*IN_DIM + i], h);
                h = fmaf(trv[j], a_row[3*IN_DIM + i], h);
                // coalesced across lanes (stride-1 in `lane`)
                msg  = fmaf(sv[j], __ldg(rw + i * OUT_DIM + lane), msg);
                curr = fmaf(tv[j], slw_col[i], curr);
            }
        }

        h = fmaxf(h, 0.f);
        // att = sigmoid(B_b + sum_l h_l * B_w_l) : warp-reduce
        float p = h * bw;
#pragma unroll
        for (int off = 16; off; off >>= 1)
            p += __shfl_xor_sync(0xffffffffu, p, off);
        const float att = 1.f / (1.f + __expf(-(p + bb)));

        const float val = curr + msg * att;
        atomicAdd(out + (size_t)t_node * OUT_DIM + lane, val);
    }
}

extern "C" void kernel_launch(void* const* d_in, const int* in_sizes, int n_in,
                              void* d_out, int out_size)
{
    const float* node_feat = (const float*)d_in[0];
    const float* ttr       = (const float*)d_in[1];
    const float* tre       = (const float*)d_in[2];
    const float* weight    = (const float*)d_in[3];
    const float* w_comp    = (const float*)d_in[4];
    const float* slw       = (const float*)d_in[5];
    const float* A_w       = (const float*)d_in[6];
    const float* A_b       = (const float*)d_in[7];
    const float* B_w       = (const float*)d_in[8];
    const float* B_b       = (const float*)d_in[9];
    const int*   edges     = (const int*)d_in[10];
    const int*   rels      = (const int*)d_in[11];
    float* out = (float*)d_out;

    const int E  = in_sizes[11];
    const int NB = in_sizes[3] / (IN_DIM * OUT_DIM);
    const int R  = in_sizes[4] / NB;

    // zero the output (poisoned by harness)
    cudaMemsetAsync(d_out, 0, (size_t)out_size * sizeof(float));

    // expand basis weights into g_relw
    k_expand_basis<<<R, 256>>>(weight, w_comp, NB);

    int sms = 148;
    cudaDeviceGetAttribute(&sms, cudaDevAttrMultiProcessorCount, 0);

    k_edges<<<sms, 256>>>(node_feat, ttr, tre, slw, A_w, A_b, B_w, B_b,
                          edges, rels, out, E);
}